// round 13
// baseline (speedup 1.0000x reference)
#include <cuda_runtime.h>
#include <cuda_fp16.h>
#include <cstdint>

// ============================================================
// out = diag(1/(rowsum(adj)+beta)) @ (adj + diag(beta)) @ x @ W + bias
// R12->R13:
//  * kernel B: B ring 3->4 stages (wait_group 2) to hide the per-iter
//    barrier/latency edge (we're at 127us vs ~90us L1/tensor floor).
//  * kernel A: grid 128->256 (M-tile 32, 256thr, warp 16x64) - was
//    0.86 CTA/SM, issue 5.6%, 22us.
// ============================================================

#define NN 8192
#define FF 256
#define MT 64             // CTA M tile (kernel B)
#define KS 32             // K per stage (kernel B)
#define KSPLIT 4096       // K per CTA (split-K x2)
#define NITER (KSPLIT / KS)  // 128
#define KSPA 40           // A row stride in halves (80B)
#define KSPB 264          // B row stride in halves (528B, trans-ldm conflict-free)
#define AS_STAGE (MT * KSPA)        // 2560 halves
#define AS_STAGE_B (AS_STAGE * 2)   // 5120 B
#define BS_STAGE (KS * KSPB)        // 8448 halves
#define BS_STAGE_B (BS_STAGE * 2)   // 16896 B

#define OFF_AS    0                           // 2 stages * 5120
#define OFF_BS    (2 * AS_STAGE_B)            // 10240, 4 stages * 16896
#define SMEM_TOTAL (OFF_BS + 4 * BS_STAGE_B)  // 77824 (x2 CTAs = 155648/SM)

// kernel A strides
#define KSPA_A 72
#define KSPB_A 264

__device__ __align__(256) float  g_y[NN * FF];        // y fp32
__device__ __align__(256) __half g_yh[NN * FF];       // y fp16 (row-major)
__device__ __align__(256) float  g_part[2 * NN * FF]; // split-K partial C
__device__ __align__(256) float  g_rs[2 * NN];        // split-K partial rowsum

// ---------------- helpers ----------------
__device__ __forceinline__ uint32_t smem_u32(const void* p) {
    uint32_t a;
    asm("{ .reg .u64 t; cvta.to.shared.u64 t, %1; cvt.u32.u64 %0, t; }" : "=r"(a) : "l"(p));
    return a;
}
__device__ __forceinline__ void cp16(uint32_t dst, const void* src) {
    asm volatile("cp.async.cg.shared.global [%0], [%1], 16;" :: "r"(dst), "l"(src));
}
__device__ __forceinline__ void cp_commit() {
    asm volatile("cp.async.commit_group;" ::: "memory");
}
__device__ __forceinline__ void ldm_x4(uint32_t* r, uint32_t addr) {
    asm volatile("ldmatrix.sync.aligned.m8n8.x4.shared.b16 {%0,%1,%2,%3}, [%4];"
        : "=r"(r[0]), "=r"(r[1]), "=r"(r[2]), "=r"(r[3]) : "r"(addr));
}
__device__ __forceinline__ void ldm_x4_t(uint32_t* r, uint32_t addr) {
    asm volatile("ldmatrix.sync.aligned.m8n8.x4.trans.shared.b16 {%0,%1,%2,%3}, [%4];"
        : "=r"(r[0]), "=r"(r[1]), "=r"(r[2]), "=r"(r[3]) : "r"(addr));
}
__device__ __forceinline__ void mma_f16(float* c, const uint32_t* a, uint32_t b0, uint32_t b1) {
    asm volatile(
        "mma.sync.aligned.m16n8k16.row.col.f32.f16.f16.f32 "
        "{%0,%1,%2,%3}, {%4,%5,%6,%7}, {%8,%9}, {%0,%1,%2,%3};"
        : "+f"(c[0]), "+f"(c[1]), "+f"(c[2]), "+f"(c[3])
        : "r"(a[0]), "r"(a[1]), "r"(a[2]), "r"(a[3]), "r"(b0), "r"(b1));
}

// ---------------- kernel A: y = x @ W (fp16 HMMA), writes g_y + g_yh ----------------
// grid 256: CTA 32x256, 256 thr, 8 warps (2m x 4n), warp tile 16x64.
__global__ void __launch_bounds__(256) gemm_y_kernel(const float* __restrict__ x,
                                                     const float* __restrict__ w)
{
    __shared__ __half xs[32 * KSPA_A];
    __shared__ __half ws[64 * KSPB_A];
    const int tid = threadIdx.x;
    const int wid = tid >> 5, lane = tid & 31;
    const int g = lane >> 2, t = lane & 3;
    const int wm = wid & 1, wn = wid >> 1;
    const int m0 = blockIdx.x * 32;
    const int mt8 = lane >> 3, r8 = lane & 7;

    const uint32_t a_lm = smem_u32(xs) +
        (((wm * 16 + (mt8 & 1) * 8 + r8) * KSPA_A + (mt8 >> 1) * 8) * 2);
    const uint32_t b_lm = smem_u32(ws) +
        (((r8 + (mt8 & 1) * 8) * KSPB_A + wn * 64 + (mt8 >> 1) * 8) * 2);

    float acc[8][4];
    #pragma unroll
    for (int j = 0; j < 8; j++)
        #pragma unroll
        for (int q = 0; q < 4; q++) acc[j][q] = 0.f;

    const int xr = tid >> 3, xq = tid & 7;     // x: 32 rows x 8 chunks
    const int wr = tid >> 2, wq = tid & 3;     // w: 64 rows x 4 chunks of 64
    for (int c = 0; c < 4; c++) {
        const int k0 = c * 64;
        {   // stage x chunk [32m][64k] fp32 -> fp16
            const float4 v0 = *(const float4*)&x[(size_t)(m0 + xr) * FF + k0 + xq * 8];
            const float4 v1 = *(const float4*)&x[(size_t)(m0 + xr) * FF + k0 + xq * 8 + 4];
            __half2 h[4];
            h[0] = __floats2half2_rn(v0.x, v0.y); h[1] = __floats2half2_rn(v0.z, v0.w);
            h[2] = __floats2half2_rn(v1.x, v1.y); h[3] = __floats2half2_rn(v1.z, v1.w);
            *(uint4*)&xs[xr * KSPA_A + xq * 8] = make_uint4(
                *(uint32_t*)&h[0], *(uint32_t*)&h[1], *(uint32_t*)&h[2], *(uint32_t*)&h[3]);
        }
        {   // stage W chunk [64k][256n] fp32 -> fp16
            #pragma unroll
            for (int j2 = 0; j2 < 8; j2++) {
                const float4 u0 = *(const float4*)&w[(size_t)(k0 + wr) * FF + wq * 64 + j2 * 8];
                const float4 u1 = *(const float4*)&w[(size_t)(k0 + wr) * FF + wq * 64 + j2 * 8 + 4];
                __half2 h[4];
                h[0] = __floats2half2_rn(u0.x, u0.y); h[1] = __floats2half2_rn(u0.z, u0.w);
                h[2] = __floats2half2_rn(u1.x, u1.y); h[3] = __floats2half2_rn(u1.z, u1.w);
                *(uint4*)&ws[wr * KSPB_A + wq * 64 + j2 * 8] = make_uint4(
                    *(uint32_t*)&h[0], *(uint32_t*)&h[1], *(uint32_t*)&h[2], *(uint32_t*)&h[3]);
            }
        }
        __syncthreads();
        #pragma unroll
        for (int kk = 0; kk < 4; kk++) {
            uint32_t a[4];
            ldm_x4(a, a_lm + kk * 32);
            uint32_t bf[4][4];
            #pragma unroll
            for (int j = 0; j < 4; j++)
                ldm_x4_t(bf[j], b_lm + (uint32_t)(kk * 16 * KSPB_A) * 2 + j * 32);
            #pragma unroll
            for (int j = 0; j < 4; j++) {
                mma_f16(acc[2 * j],     a, bf[j][0], bf[j][1]);
                mma_f16(acc[2 * j + 1], a, bf[j][2], bf[j][3]);
            }
        }
        __syncthreads();
    }

    // epilogue: write fp32 g_y and fp16 g_yh
    const int lm = wm * 16 + g;
    #pragma unroll
    for (int nj = 0; nj < 8; nj++) {
        const int n = wn * 64 + nj * 8 + 2 * t;
        const float* cc = acc[nj];
        const size_t b0 = (size_t)(m0 + lm) * FF + n;
        const size_t b1 = (size_t)(m0 + lm + 8) * FF + n;
        *(float2*)&g_y[b0] = make_float2(cc[0], cc[1]);
        *(float2*)&g_y[b1] = make_float2(cc[2], cc[3]);
        __half2 h0 = __floats2half2_rn(cc[0], cc[1]);
        __half2 h1 = __floats2half2_rn(cc[2], cc[3]);
        *(__half2*)&g_yh[b0] = h0;
        *(__half2*)&g_yh[b1] = h1;
    }
}

// ---------------- kernel B: partial C = adj[:, kslice] @ y[kslice] ----------------
// 256 thr, 8 warps (2m x 4n), warp tile 32x64, CTA 64x256, split-K x2, 4-stage B ring.
__global__ void __launch_bounds__(256, 2) gcn_mma_kernel(
    const float* __restrict__ adj)
{
    extern __shared__ char smem[];
    __half* As = (__half*)(smem + OFF_AS);
    const uint32_t sb = smem_u32(smem);

    const int tid = threadIdx.x;
    const int wid = tid >> 5, lane = tid & 31;
    const int g = lane >> 2, t = lane & 3;
    const int wm = wid & 1, wn = wid >> 1;      // 2 m-warps x 4 n-warps
    const int m0 = blockIdx.x * MT;
    const int ksl = blockIdx.y;                 // 0 or 1
    const int k0 = ksl * KSPLIT;

    // A: 4 threads per row, 8 floats each (KS=32)
    const int ar = tid >> 2, acq = tid & 3;
    const float* aptr = adj + (size_t)(m0 + ar) * NN + k0 + acq * 8;
    __half* const a_st = As + ar * KSPA + acq * 8;
    // B: 32 threads per k-row, contiguous 16B; 8 rows/pass, 4 passes/stage
    const int br = tid >> 5, bq = tid & 31;
    const __half* bptr = g_yh + (size_t)(k0 + br) * FF + bq * 8;
    const uint32_t b_dst = sb + OFF_BS + (br * KSPB) * 2 + bq * 16;

    const int mt8 = lane >> 3, r8 = lane & 7;
    const uint32_t a_lm = sb + OFF_AS +
        (((wm * 32 + (mt8 & 1) * 8 + r8) * KSPA + (mt8 >> 1) * 8) * 2);
    const uint32_t b_lm = sb + OFF_BS +
        (((r8 + (mt8 & 1) * 8) * KSPB + wn * 64 + (mt8 >> 1) * 8) * 2);

    float rs_local = 0.f;
    float acc[2][8][4];
    #pragma unroll
    for (int i = 0; i < 2; i++)
        #pragma unroll
        for (int j = 0; j < 8; j++)
            #pragma unroll
            for (int q = 0; q < 4; q++) acc[i][j][q] = 0.f;

    float4 ra[2][2];

    // ---- prologue: B stages 0,1,2 via cp.async; A stages 0,1 via LDG ----
    #pragma unroll
    for (int s = 0; s < 3; s++) {
        #pragma unroll
        for (int c = 0; c < 4; c++)
            cp16(b_dst + s * BS_STAGE_B + c * (8 * KSPB * 2),
                 (const void*)(bptr + ((size_t)s * KS + c * 8) * FF));
        cp_commit();
    }
    #pragma unroll
    for (int s = 0; s < 2; s++) {
        ra[s][0] = *(const float4*)(aptr + (size_t)s * KS);
        ra[s][1] = *(const float4*)(aptr + (size_t)s * KS + 4);
    }
    {   // STS A stage 0 + rowsum
        const float4 v0 = ra[0][0], v1 = ra[0][1];
        rs_local += v0.x + v0.y + v0.z + v0.w + v1.x + v1.y + v1.z + v1.w;
        __half2 h[4];
        h[0] = __floats2half2_rn(v0.x, v0.y); h[1] = __floats2half2_rn(v0.z, v0.w);
        h[2] = __floats2half2_rn(v1.x, v1.y); h[3] = __floats2half2_rn(v1.z, v1.w);
        *(uint4*)a_st = make_uint4(*(uint32_t*)&h[0], *(uint32_t*)&h[1],
                                   *(uint32_t*)&h[2], *(uint32_t*)&h[3]);
    }

    // ---- main loop (single barrier, 4-stage B ring, 2 stages in flight) ----
    for (int i = 0; i < NITER; i++) {
        const int bbuf = i & 3;

        if (i + 2 < NITER) {
            const float* ap = aptr + (size_t)(i + 2) * KS;
            ra[i & 1][0] = *(const float4*)(ap);
            ra[i & 1][1] = *(const float4*)(ap + 4);
        }

        if (i < NITER - 2)       { asm volatile("cp.async.wait_group 2;" ::: "memory"); }
        else if (i == NITER - 2) { asm volatile("cp.async.wait_group 1;" ::: "memory"); }
        else                     { asm volatile("cp.async.wait_group 0;" ::: "memory"); }
        __syncthreads();

        if (i + 1 < NITER) {   // STS A stage i+1 + rowsum
            const float4 v0 = ra[(i + 1) & 1][0], v1 = ra[(i + 1) & 1][1];
            rs_local += v0.x + v0.y + v0.z + v0.w + v1.x + v1.y + v1.z + v1.w;
            __half2 h[4];
            h[0] = __floats2half2_rn(v0.x, v0.y); h[1] = __floats2half2_rn(v0.z, v0.w);
            h[2] = __floats2half2_rn(v1.x, v1.y); h[3] = __floats2half2_rn(v1.z, v1.w);
            *(uint4*)(a_st + ((i + 1) & 1) * AS_STAGE) = make_uint4(
                *(uint32_t*)&h[0], *(uint32_t*)&h[1], *(uint32_t*)&h[2], *(uint32_t*)&h[3]);
        }
        if (i + 3 < NITER) {   // cp.async B stage i+3 into buf (i+3)&3 (== i-1, free)
            const uint32_t bd = b_dst + ((i + 3) & 3) * BS_STAGE_B;
            const __half* bp = bptr + (size_t)(i + 3) * KS * FF;
            #pragma unroll
            for (int c = 0; c < 4; c++)
                cp16(bd + c * (8 * KSPB * 2), (const void*)(bp + (size_t)c * 8 * FF));
            cp_commit();
        }

        // ---- compute stage i (warp tile 32x64, 2 kk chunks) ----
        const uint32_t aB = a_lm + (i & 1) * AS_STAGE_B;
        const uint32_t bB = b_lm + bbuf * BS_STAGE_B;
        #pragma unroll
        for (int kk = 0; kk < 2; kk++) {
            uint32_t a0[4], a1[4];
            ldm_x4(a0, aB + kk * 32);
            ldm_x4(a1, aB + kk * 32 + 16 * KSPA * 2);
            uint32_t bf[4][4];
            #pragma unroll
            for (int j = 0; j < 4; j++)
                ldm_x4_t(bf[j], bB + (uint32_t)(kk * 16 * KSPB) * 2 + j * 32);
            #pragma unroll
            for (int j = 0; j < 4; j++) {
                mma_f16(acc[0][2 * j],     a0, bf[j][0], bf[j][1]);
                mma_f16(acc[0][2 * j + 1], a0, bf[j][2], bf[j][3]);
                mma_f16(acc[1][2 * j],     a1, bf[j][0], bf[j][1]);
                mma_f16(acc[1][2 * j + 1], a1, bf[j][2], bf[j][3]);
            }
        }
    }

    // ---- partial rowsum: 4 consecutive lanes per row ----
    float rs = rs_local;
    rs += __shfl_xor_sync(0xffffffffu, rs, 1);
    rs += __shfl_xor_sync(0xffffffffu, rs, 2);
    if ((tid & 3) == 0) g_rs[(size_t)ksl * NN + m0 + ar] = rs;

    // ---- write partial C ----
    float* pout = g_part + (size_t)ksl * NN * FF;
    #pragma unroll
    for (int mi = 0; mi < 2; mi++) {
        const int lm = wm * 32 + mi * 16 + g;
        #pragma unroll
        for (int nj = 0; nj < 8; nj++) {
            const int n = wn * 64 + nj * 8 + 2 * t;
            const float* cc = acc[mi][nj];
            *(float2*)&pout[(size_t)(m0 + lm) * FF + n]     = make_float2(cc[0], cc[1]);
            *(float2*)&pout[(size_t)(m0 + lm + 8) * FF + n] = make_float2(cc[2], cc[3]);
        }
    }
}

// ---------------- combine: out = scale*(P0+P1+beta*y) + bias ----------------
__global__ void __launch_bounds__(256) combine_kernel(
    const float* __restrict__ beta,
    const float* __restrict__ bias,
    float* __restrict__ out)
{
    const int idx = blockIdx.x * 256 + threadIdx.x;   // 1 thread = 4 floats
    const int m = idx >> 6;
    const int n = (idx & 63) * 4;
    const float be = beta[m];
    const float sc = 1.0f / (g_rs[m] + g_rs[NN + m] + be);
    const size_t off = (size_t)m * FF + n;
    const float4 p0 = *(const float4*)&g_part[off];
    const float4 p1 = *(const float4*)&g_part[(size_t)NN * FF + off];
    const float4 yv = *(const float4*)&g_y[off];
    const float4 bv = *(const float4*)&bias[n];
    float4 o;
    o.x = sc * (p0.x + p1.x + be * yv.x) + bv.x;
    o.y = sc * (p0.y + p1.y + be * yv.y) + bv.y;
    o.z = sc * (p0.z + p1.z + be * yv.z) + bv.z;
    o.w = sc * (p0.w + p1.w + be * yv.w) + bv.w;
    *(float4*)&out[off] = o;
}

// ---------------- launch ----------------
extern "C" void kernel_launch(void* const* d_in, const int* in_sizes, int n_in,
                              void* d_out, int out_size)
{
    const float *x = nullptr, *adj = nullptr, *w = nullptr, *bias = nullptr, *beta = nullptr;
    for (int i = 0; i < n_in; i++) {
        switch (in_sizes[i]) {
            case NN * FF:   x    = (const float*)d_in[i]; break;
            case 67108864:  adj  = (const float*)d_in[i]; break;
            case FF * FF:   w    = (const float*)d_in[i]; break;
            case FF:        bias = (const float*)d_in[i]; break;
            case NN:        beta = (const float*)d_in[i]; break;
            default: break;
        }
    }
    float* out = (float*)d_out;

    cudaFuncSetAttribute(gcn_mma_kernel, cudaFuncAttributeMaxDynamicSharedMemorySize, SMEM_TOTAL);

    gemm_y_kernel<<<NN / 32, 256>>>(x, w);
    gcn_mma_kernel<<<dim3(NN / MT, 2), 256, SMEM_TOTAL>>>(adj);
    combine_kernel<<<(NN * FF) / (256 * 4), 256>>>(beta, bias, out);
}

// round 14
// speedup vs baseline: 1.0601x; 1.0601x over previous
#include <cuda_runtime.h>
#include <cuda_fp16.h>
#include <cstdint>

// ============================================================
// out = diag(1/(rowsum(adj)+beta)) @ (adj + diag(beta)) @ x @ W + bias
// R13->R14:
//  * kernel B: unchanged from R13 (4-stage ring, ~119us measured).
//  * kernel A: R13's regrid regressed (every CTA staged ALL of W ->
//    L1 68.6%). Now split N: CTA 64m x 128n, grid (128,2)=256 CTAs,
//    per-CTA W staging halved vs R13. 256thr, warp tile 32x32.
// ============================================================

#define NN 8192
#define FF 256
#define MT 64             // CTA M tile (kernel B)
#define KS 32             // K per stage (kernel B)
#define KSPLIT 4096       // K per CTA (split-K x2)
#define NITER (KSPLIT / KS)  // 128
#define KSPA 40           // A row stride in halves (80B)
#define KSPB 264          // B row stride in halves (528B, trans-ldm conflict-free)
#define AS_STAGE (MT * KSPA)        // 2560 halves
#define AS_STAGE_B (AS_STAGE * 2)   // 5120 B
#define BS_STAGE (KS * KSPB)        // 8448 halves
#define BS_STAGE_B (BS_STAGE * 2)   // 16896 B

#define OFF_AS    0                           // 2 stages * 5120
#define OFF_BS    (2 * AS_STAGE_B)            // 10240, 4 stages * 16896
#define SMEM_TOTAL (OFF_BS + 4 * BS_STAGE_B)  // 77824 (x2 CTAs = 155648/SM)

// kernel A strides
#define KSPA_A 72
#define KSPB_A 136        // 272B rows: +16B/row shift, trans-ldm conflict-free

__device__ __align__(256) float  g_y[NN * FF];        // y fp32
__device__ __align__(256) __half g_yh[NN * FF];       // y fp16 (row-major)
__device__ __align__(256) float  g_part[2 * NN * FF]; // split-K partial C
__device__ __align__(256) float  g_rs[2 * NN];        // split-K partial rowsum

// ---------------- helpers ----------------
__device__ __forceinline__ uint32_t smem_u32(const void* p) {
    uint32_t a;
    asm("{ .reg .u64 t; cvta.to.shared.u64 t, %1; cvt.u32.u64 %0, t; }" : "=r"(a) : "l"(p));
    return a;
}
__device__ __forceinline__ void cp16(uint32_t dst, const void* src) {
    asm volatile("cp.async.cg.shared.global [%0], [%1], 16;" :: "r"(dst), "l"(src));
}
__device__ __forceinline__ void cp_commit() {
    asm volatile("cp.async.commit_group;" ::: "memory");
}
__device__ __forceinline__ void ldm_x4(uint32_t* r, uint32_t addr) {
    asm volatile("ldmatrix.sync.aligned.m8n8.x4.shared.b16 {%0,%1,%2,%3}, [%4];"
        : "=r"(r[0]), "=r"(r[1]), "=r"(r[2]), "=r"(r[3]) : "r"(addr));
}
__device__ __forceinline__ void ldm_x4_t(uint32_t* r, uint32_t addr) {
    asm volatile("ldmatrix.sync.aligned.m8n8.x4.trans.shared.b16 {%0,%1,%2,%3}, [%4];"
        : "=r"(r[0]), "=r"(r[1]), "=r"(r[2]), "=r"(r[3]) : "r"(addr));
}
__device__ __forceinline__ void mma_f16(float* c, const uint32_t* a, uint32_t b0, uint32_t b1) {
    asm volatile(
        "mma.sync.aligned.m16n8k16.row.col.f32.f16.f16.f32 "
        "{%0,%1,%2,%3}, {%4,%5,%6,%7}, {%8,%9}, {%0,%1,%2,%3};"
        : "+f"(c[0]), "+f"(c[1]), "+f"(c[2]), "+f"(c[3])
        : "r"(a[0]), "r"(a[1]), "r"(a[2]), "r"(a[3]), "r"(b0), "r"(b1));
}

// ---------------- kernel A: y = x @ W (fp16 HMMA), writes g_y + g_yh ----------------
// CTA 64m x 128n, grid (128,2), 256 thr, 8 warps (2m x 4n), warp tile 32x32.
__global__ void __launch_bounds__(256) gemm_y_kernel(const float* __restrict__ x,
                                                     const float* __restrict__ w)
{
    __shared__ __half xs[64 * KSPA_A];    // [64m][64k]
    __shared__ __half ws[64 * KSPB_A];    // [64k][128n]
    const int tid = threadIdx.x;
    const int wid = tid >> 5, lane = tid & 31;
    const int g = lane >> 2, t = lane & 3;
    const int wm = wid & 1, wn = wid >> 1;
    const int m0 = blockIdx.x * 64;
    const int n0 = blockIdx.y * 128;
    const int mt8 = lane >> 3, r8 = lane & 7;

    const uint32_t a_lm = smem_u32(xs) +
        (((wm * 32 + (mt8 & 1) * 8 + r8) * KSPA_A + (mt8 >> 1) * 8) * 2);
    const uint32_t b_lm = smem_u32(ws) +
        (((r8 + (mt8 & 1) * 8) * KSPB_A + wn * 32 + (lane >> 4) * 8) * 2);

    float acc[2][4][4];
    #pragma unroll
    for (int i = 0; i < 2; i++)
        #pragma unroll
        for (int j = 0; j < 4; j++)
            #pragma unroll
            for (int q = 0; q < 4; q++) acc[i][j][q] = 0.f;

    const int xr = tid >> 2, xq = (tid & 3) * 16;   // x: 4 thr/row, 16 floats each
    const int wr = tid >> 2, wq = (tid & 3) * 32;   // W: 4 thr/row, 32 floats each
    for (int c = 0; c < 4; c++) {
        const int k0 = c * 64;
        {   // stage x chunk [64m][64k] fp32 -> fp16 (2 x uint4)
            #pragma unroll
            for (int j2 = 0; j2 < 2; j2++) {
                const float4 v0 = *(const float4*)&x[(size_t)(m0 + xr) * FF + k0 + xq + j2 * 8];
                const float4 v1 = *(const float4*)&x[(size_t)(m0 + xr) * FF + k0 + xq + j2 * 8 + 4];
                __half2 h[4];
                h[0] = __floats2half2_rn(v0.x, v0.y); h[1] = __floats2half2_rn(v0.z, v0.w);
                h[2] = __floats2half2_rn(v1.x, v1.y); h[3] = __floats2half2_rn(v1.z, v1.w);
                *(uint4*)&xs[xr * KSPA_A + xq + j2 * 8] = make_uint4(
                    *(uint32_t*)&h[0], *(uint32_t*)&h[1], *(uint32_t*)&h[2], *(uint32_t*)&h[3]);
            }
        }
        {   // stage W chunk [64k][128n] fp32 -> fp16 (4 x uint4)
            #pragma unroll
            for (int j2 = 0; j2 < 4; j2++) {
                const float4 u0 = *(const float4*)&w[(size_t)(k0 + wr) * FF + n0 + wq + j2 * 8];
                const float4 u1 = *(const float4*)&w[(size_t)(k0 + wr) * FF + n0 + wq + j2 * 8 + 4];
                __half2 h[4];
                h[0] = __floats2half2_rn(u0.x, u0.y); h[1] = __floats2half2_rn(u0.z, u0.w);
                h[2] = __floats2half2_rn(u1.x, u1.y); h[3] = __floats2half2_rn(u1.z, u1.w);
                *(uint4*)&ws[wr * KSPB_A + wq + j2 * 8] = make_uint4(
                    *(uint32_t*)&h[0], *(uint32_t*)&h[1], *(uint32_t*)&h[2], *(uint32_t*)&h[3]);
            }
        }
        __syncthreads();
        #pragma unroll
        for (int kk = 0; kk < 4; kk++) {
            uint32_t a0[4], a1[4];
            ldm_x4(a0, a_lm + kk * 32);
            ldm_x4(a1, a_lm + kk * 32 + 16 * KSPA_A * 2);
            uint32_t bf[2][4];
            #pragma unroll
            for (int p = 0; p < 2; p++)
                ldm_x4_t(bf[p], b_lm + (uint32_t)(kk * 16 * KSPB_A + p * 16) * 2);
            #pragma unroll
            for (int p = 0; p < 2; p++) {
                mma_f16(acc[0][2 * p],     a0, bf[p][0], bf[p][1]);
                mma_f16(acc[1][2 * p],     a1, bf[p][0], bf[p][1]);
                mma_f16(acc[0][2 * p + 1], a0, bf[p][2], bf[p][3]);
                mma_f16(acc[1][2 * p + 1], a1, bf[p][2], bf[p][3]);
            }
        }
        __syncthreads();
    }

    #pragma unroll
    for (int mi = 0; mi < 2; mi++) {
        const int lm = wm * 32 + mi * 16 + g;
        #pragma unroll
        for (int nj = 0; nj < 4; nj++) {
            const int n = n0 + wn * 32 + nj * 8 + 2 * t;
            const float* cc = acc[mi][nj];
            const size_t b0 = (size_t)(m0 + lm) * FF + n;
            const size_t b1 = (size_t)(m0 + lm + 8) * FF + n;
            *(float2*)&g_y[b0] = make_float2(cc[0], cc[1]);
            *(float2*)&g_y[b1] = make_float2(cc[2], cc[3]);
            __half2 h0 = __floats2half2_rn(cc[0], cc[1]);
            __half2 h1 = __floats2half2_rn(cc[2], cc[3]);
            *(__half2*)&g_yh[b0] = h0;
            *(__half2*)&g_yh[b1] = h1;
        }
    }
}

// ---------------- kernel B: partial C = adj[:, kslice] @ y[kslice] ----------------
// 256 thr, 8 warps (2m x 4n), warp tile 32x64, CTA 64x256, split-K x2, 4-stage B ring.
__global__ void __launch_bounds__(256, 2) gcn_mma_kernel(
    const float* __restrict__ adj)
{
    extern __shared__ char smem[];
    __half* As = (__half*)(smem + OFF_AS);
    const uint32_t sb = smem_u32(smem);

    const int tid = threadIdx.x;
    const int wid = tid >> 5, lane = tid & 31;
    const int g = lane >> 2, t = lane & 3;
    const int wm = wid & 1, wn = wid >> 1;      // 2 m-warps x 4 n-warps
    const int m0 = blockIdx.x * MT;
    const int ksl = blockIdx.y;                 // 0 or 1
    const int k0 = ksl * KSPLIT;

    // A: 4 threads per row, 8 floats each (KS=32)
    const int ar = tid >> 2, acq = tid & 3;
    const float* aptr = adj + (size_t)(m0 + ar) * NN + k0 + acq * 8;
    __half* const a_st = As + ar * KSPA + acq * 8;
    // B: 32 threads per k-row, contiguous 16B; 8 rows/pass, 4 passes/stage
    const int br = tid >> 5, bq = tid & 31;
    const __half* bptr = g_yh + (size_t)(k0 + br) * FF + bq * 8;
    const uint32_t b_dst = sb + OFF_BS + (br * KSPB) * 2 + bq * 16;

    const int mt8 = lane >> 3, r8 = lane & 7;
    const uint32_t a_lm = sb + OFF_AS +
        (((wm * 32 + (mt8 & 1) * 8 + r8) * KSPA + (mt8 >> 1) * 8) * 2);
    const uint32_t b_lm = sb + OFF_BS +
        (((r8 + (mt8 & 1) * 8) * KSPB + wn * 64 + (mt8 >> 1) * 8) * 2);

    float rs_local = 0.f;
    float acc[2][8][4];
    #pragma unroll
    for (int i = 0; i < 2; i++)
        #pragma unroll
        for (int j = 0; j < 8; j++)
            #pragma unroll
            for (int q = 0; q < 4; q++) acc[i][j][q] = 0.f;

    float4 ra[2][2];

    // ---- prologue: B stages 0,1,2 via cp.async; A stages 0,1 via LDG ----
    #pragma unroll
    for (int s = 0; s < 3; s++) {
        #pragma unroll
        for (int c = 0; c < 4; c++)
            cp16(b_dst + s * BS_STAGE_B + c * (8 * KSPB * 2),
                 (const void*)(bptr + ((size_t)s * KS + c * 8) * FF));
        cp_commit();
    }
    #pragma unroll
    for (int s = 0; s < 2; s++) {
        ra[s][0] = *(const float4*)(aptr + (size_t)s * KS);
        ra[s][1] = *(const float4*)(aptr + (size_t)s * KS + 4);
    }
    {   // STS A stage 0 + rowsum
        const float4 v0 = ra[0][0], v1 = ra[0][1];
        rs_local += v0.x + v0.y + v0.z + v0.w + v1.x + v1.y + v1.z + v1.w;
        __half2 h[4];
        h[0] = __floats2half2_rn(v0.x, v0.y); h[1] = __floats2half2_rn(v0.z, v0.w);
        h[2] = __floats2half2_rn(v1.x, v1.y); h[3] = __floats2half2_rn(v1.z, v1.w);
        *(uint4*)a_st = make_uint4(*(uint32_t*)&h[0], *(uint32_t*)&h[1],
                                   *(uint32_t*)&h[2], *(uint32_t*)&h[3]);
    }

    // ---- main loop (single barrier, 4-stage B ring, 2 stages in flight) ----
    for (int i = 0; i < NITER; i++) {
        const int bbuf = i & 3;

        if (i + 2 < NITER) {
            const float* ap = aptr + (size_t)(i + 2) * KS;
            ra[i & 1][0] = *(const float4*)(ap);
            ra[i & 1][1] = *(const float4*)(ap + 4);
        }

        if (i < NITER - 2)       { asm volatile("cp.async.wait_group 2;" ::: "memory"); }
        else if (i == NITER - 2) { asm volatile("cp.async.wait_group 1;" ::: "memory"); }
        else                     { asm volatile("cp.async.wait_group 0;" ::: "memory"); }
        __syncthreads();

        if (i + 1 < NITER) {   // STS A stage i+1 + rowsum
            const float4 v0 = ra[(i + 1) & 1][0], v1 = ra[(i + 1) & 1][1];
            rs_local += v0.x + v0.y + v0.z + v0.w + v1.x + v1.y + v1.z + v1.w;
            __half2 h[4];
            h[0] = __floats2half2_rn(v0.x, v0.y); h[1] = __floats2half2_rn(v0.z, v0.w);
            h[2] = __floats2half2_rn(v1.x, v1.y); h[3] = __floats2half2_rn(v1.z, v1.w);
            *(uint4*)(a_st + ((i + 1) & 1) * AS_STAGE) = make_uint4(
                *(uint32_t*)&h[0], *(uint32_t*)&h[1], *(uint32_t*)&h[2], *(uint32_t*)&h[3]);
        }
        if (i + 3 < NITER) {   // cp.async B stage i+3 into buf (i+3)&3 (== i-1, free)
            const uint32_t bd = b_dst + ((i + 3) & 3) * BS_STAGE_B;
            const __half* bp = bptr + (size_t)(i + 3) * KS * FF;
            #pragma unroll
            for (int c = 0; c < 4; c++)
                cp16(bd + c * (8 * KSPB * 2), (const void*)(bp + (size_t)c * 8 * FF));
            cp_commit();
        }

        // ---- compute stage i (warp tile 32x64, 2 kk chunks) ----
        const uint32_t aB = a_lm + (i & 1) * AS_STAGE_B;
        const uint32_t bB = b_lm + bbuf * BS_STAGE_B;
        #pragma unroll
        for (int kk = 0; kk < 2; kk++) {
            uint32_t a0[4], a1[4];
            ldm_x4(a0, aB + kk * 32);
            ldm_x4(a1, aB + kk * 32 + 16 * KSPA * 2);
            uint32_t bf[4][4];
            #pragma unroll
            for (int j = 0; j < 4; j++)
                ldm_x4_t(bf[j], bB + (uint32_t)(kk * 16 * KSPB) * 2 + j * 32);
            #pragma unroll
            for (int j = 0; j < 4; j++) {
                mma_f16(acc[0][2 * j],     a0, bf[j][0], bf[j][1]);
                mma_f16(acc[0][2 * j + 1], a0, bf[j][2], bf[j][3]);
                mma_f16(acc[1][2 * j],     a1, bf[j][0], bf[j][1]);
                mma_f16(acc[1][2 * j + 1], a1, bf[j][2], bf[j][3]);
            }
        }
    }

    // ---- partial rowsum: 4 consecutive lanes per row ----
    float rs = rs_local;
    rs += __shfl_xor_sync(0xffffffffu, rs, 1);
    rs += __shfl_xor_sync(0xffffffffu, rs, 2);
    if ((tid & 3) == 0) g_rs[(size_t)ksl * NN + m0 + ar] = rs;

    // ---- write partial C ----
    float* pout = g_part + (size_t)ksl * NN * FF;
    #pragma unroll
    for (int mi = 0; mi < 2; mi++) {
        const int lm = wm * 32 + mi * 16 + g;
        #pragma unroll
        for (int nj = 0; nj < 8; nj++) {
            const int n = wn * 64 + nj * 8 + 2 * t;
            const float* cc = acc[mi][nj];
            *(float2*)&pout[(size_t)(m0 + lm) * FF + n]     = make_float2(cc[0], cc[1]);
            *(float2*)&pout[(size_t)(m0 + lm + 8) * FF + n] = make_float2(cc[2], cc[3]);
        }
    }
}

// ---------------- combine: out = scale*(P0+P1+beta*y) + bias ----------------
__global__ void __launch_bounds__(256) combine_kernel(
    const float* __restrict__ beta,
    const float* __restrict__ bias,
    float* __restrict__ out)
{
    const int idx = blockIdx.x * 256 + threadIdx.x;   // 1 thread = 4 floats
    const int m = idx >> 6;
    const int n = (idx & 63) * 4;
    const float be = beta[m];
    const float sc = 1.0f / (g_rs[m] + g_rs[NN + m] + be);
    const size_t off = (size_t)m * FF + n;
    const float4 p0 = *(const float4*)&g_part[off];
    const float4 p1 = *(const float4*)&g_part[(size_t)NN * FF + off];
    const float4 yv = *(const float4*)&g_y[off];
    const float4 bv = *(const float4*)&bias[n];
    float4 o;
    o.x = sc * (p0.x + p1.x + be * yv.x) + bv.x;
    o.y = sc * (p0.y + p1.y + be * yv.y) + bv.y;
    o.z = sc * (p0.z + p1.z + be * yv.z) + bv.z;
    o.w = sc * (p0.w + p1.w + be * yv.w) + bv.w;
    *(float4*)&out[off] = o;
}

// ---------------- launch ----------------
extern "C" void kernel_launch(void* const* d_in, const int* in_sizes, int n_in,
                              void* d_out, int out_size)
{
    const float *x = nullptr, *adj = nullptr, *w = nullptr, *bias = nullptr, *beta = nullptr;
    for (int i = 0; i < n_in; i++) {
        switch (in_sizes[i]) {
            case NN * FF:   x    = (const float*)d_in[i]; break;
            case 67108864:  adj  = (const float*)d_in[i]; break;
            case FF * FF:   w    = (const float*)d_in[i]; break;
            case FF:        bias = (const float*)d_in[i]; break;
            case NN:        beta = (const float*)d_in[i]; break;
            default: break;
        }
    }
    float* out = (float*)d_out;

    cudaFuncSetAttribute(gcn_mma_kernel, cudaFuncAttributeMaxDynamicSharedMemorySize, SMEM_TOTAL);

    gemm_y_kernel<<<dim3(NN / 64, 2), 256>>>(x, w);
    gcn_mma_kernel<<<dim3(NN / MT, 2), 256, SMEM_TOTAL>>>(adj);
    combine_kernel<<<(NN * FF) / (256 * 4), 256>>>(beta, bias, out);
}

// round 15
// speedup vs baseline: 1.1244x; 1.0607x over previous
#include <cuda_runtime.h>
#include <cuda_fp16.h>
#include <cstdint>

// ============================================================
// out = diag(1/(rowsum(adj)+beta)) @ (adj + diag(beta)) @ x @ W + bias
// R14->R15:
//  * kernel B unchanged (119us measured, 4-stage ring).
//  * NEW fp16 pre-pass (x->g_xh, W->g_wh).
//  * kernel A rebuilt: whole K=256 staged in ONE cp.async burst
//    (70.7KB smem, 2 CTAs/SM, grid 512), ONE barrier, 16 straight
//    HMMA chunks. Was 4 chunks x 2 barriers, 22us.
//  * g_y fp32 dropped; combine reads fp16 y (beta*y term tolerates it).
// ============================================================

#define NN 8192
#define FF 256
#define MT 64             // CTA M tile (kernel B)
#define KS 32             // K per stage (kernel B)
#define KSPLIT 4096       // K per CTA (split-K x2)
#define NITER (KSPLIT / KS)  // 128
#define KSPA 40           // A row stride in halves (80B)
#define KSPB 264          // B row stride in halves (528B, trans-ldm conflict-free)
#define AS_STAGE (MT * KSPA)        // 2560 halves
#define AS_STAGE_B (AS_STAGE * 2)   // 5120 B
#define BS_STAGE (KS * KSPB)        // 8448 halves
#define BS_STAGE_B (BS_STAGE * 2)   // 16896 B

#define OFF_AS    0                           // 2 stages * 5120
#define OFF_BS    (2 * AS_STAGE_B)            // 10240, 4 stages * 16896
#define SMEM_TOTAL (OFF_BS + 4 * BS_STAGE_B)  // 77824 (x2 CTAs = 155648/SM)

// kernel A (single-load) layout
#define KSPX 264          // x row stride in halves (528B)
#define KSPW 72           // W row stride in halves (144B)
#define OFF_WS (64 * KSPX * 2)                       // 33792
#define SMEM_A_TOTAL (OFF_WS + 256 * KSPW * 2)       // 70656 (x2 = 141312/SM)

__device__ __align__(256) __half g_xh[NN * FF];       // x fp16
__device__ __align__(256) __half g_wh[FF * FF];       // W fp16
__device__ __align__(256) __half g_yh[NN * FF];       // y fp16 (row-major)
__device__ __align__(256) float  g_part[2 * NN * FF]; // split-K partial C
__device__ __align__(256) float  g_rs[2 * NN];        // split-K partial rowsum

// ---------------- helpers ----------------
__device__ __forceinline__ uint32_t smem_u32(const void* p) {
    uint32_t a;
    asm("{ .reg .u64 t; cvta.to.shared.u64 t, %1; cvt.u32.u64 %0, t; }" : "=r"(a) : "l"(p));
    return a;
}
__device__ __forceinline__ void cp16(uint32_t dst, const void* src) {
    asm volatile("cp.async.cg.shared.global [%0], [%1], 16;" :: "r"(dst), "l"(src));
}
__device__ __forceinline__ void cp_commit() {
    asm volatile("cp.async.commit_group;" ::: "memory");
}
__device__ __forceinline__ void ldm_x4(uint32_t* r, uint32_t addr) {
    asm volatile("ldmatrix.sync.aligned.m8n8.x4.shared.b16 {%0,%1,%2,%3}, [%4];"
        : "=r"(r[0]), "=r"(r[1]), "=r"(r[2]), "=r"(r[3]) : "r"(addr));
}
__device__ __forceinline__ void ldm_x4_t(uint32_t* r, uint32_t addr) {
    asm volatile("ldmatrix.sync.aligned.m8n8.x4.trans.shared.b16 {%0,%1,%2,%3}, [%4];"
        : "=r"(r[0]), "=r"(r[1]), "=r"(r[2]), "=r"(r[3]) : "r"(addr));
}
__device__ __forceinline__ void mma_f16(float* c, const uint32_t* a, uint32_t b0, uint32_t b1) {
    asm volatile(
        "mma.sync.aligned.m16n8k16.row.col.f32.f16.f16.f32 "
        "{%0,%1,%2,%3}, {%4,%5,%6,%7}, {%8,%9}, {%0,%1,%2,%3};"
        : "+f"(c[0]), "+f"(c[1]), "+f"(c[2]), "+f"(c[3])
        : "r"(a[0]), "r"(a[1]), "r"(a[2]), "r"(a[3]), "r"(b0), "r"(b1));
}

// ---------------- pre-pass: fp32 -> fp16 for x and W ----------------
__global__ void __launch_bounds__(256) convert_kernel(const float* __restrict__ x,
                                                      const float* __restrict__ w)
{
    const int idx = blockIdx.x * 256 + threadIdx.x;   // 1 thread = 8 floats
    const int NX = NN * FF / 8;                        // 262144
    if (idx < NX) {
        const float4 v0 = *(const float4*)&x[(size_t)idx * 8];
        const float4 v1 = *(const float4*)&x[(size_t)idx * 8 + 4];
        __half2 h[4];
        h[0] = __floats2half2_rn(v0.x, v0.y); h[1] = __floats2half2_rn(v0.z, v0.w);
        h[2] = __floats2half2_rn(v1.x, v1.y); h[3] = __floats2half2_rn(v1.z, v1.w);
        *(uint4*)&g_xh[(size_t)idx * 8] = make_uint4(
            *(uint32_t*)&h[0], *(uint32_t*)&h[1], *(uint32_t*)&h[2], *(uint32_t*)&h[3]);
    } else {
        const int j = idx - NX;                        // < 8192
        const float4 v0 = *(const float4*)&w[(size_t)j * 8];
        const float4 v1 = *(const float4*)&w[(size_t)j * 8 + 4];
        __half2 h[4];
        h[0] = __floats2half2_rn(v0.x, v0.y); h[1] = __floats2half2_rn(v0.z, v0.w);
        h[2] = __floats2half2_rn(v1.x, v1.y); h[3] = __floats2half2_rn(v1.z, v1.w);
        *(uint4*)&g_wh[(size_t)j * 8] = make_uint4(
            *(uint32_t*)&h[0], *(uint32_t*)&h[1], *(uint32_t*)&h[2], *(uint32_t*)&h[3]);
    }
}

// ---------------- kernel A: y = x @ W (fp16 HMMA), single-barrier ----------------
// CTA 64m x 64n, grid (128, 4) = 512 CTAs, 256 thr, 8 warps (2m x 4n), warp 32x16.
__global__ void __launch_bounds__(256, 2) gemm_y_kernel()
{
    extern __shared__ char smem[];
    const uint32_t sb = smem_u32(smem);
    const int tid = threadIdx.x;
    const int wid = tid >> 5, lane = tid & 31;
    const int g = lane >> 2, t = lane & 3;
    const int wm = wid & 1, wn = wid >> 1;
    const int m0 = blockIdx.x * 64;
    const int n0 = blockIdx.y * 64;
    const int mt8 = lane >> 3, r8 = lane & 7;

    // ---- one cp.async burst: full x-tile [64m][256k] + W-slice [256k][64n] ----
    {
        const int xr = tid >> 5, xc = tid & 31;        // 8 rows/pass, 32 chunks/row
        #pragma unroll
        for (int p = 0; p < 8; p++) {
            const int row = p * 8 + xr;
            cp16(sb + (uint32_t)(row * KSPX + xc * 8) * 2,
                 (const void*)(g_xh + (size_t)(m0 + row) * FF + xc * 8));
        }
        const int wr = tid >> 3, wc = tid & 7;         // 32 rows/pass, 8 chunks/row
        #pragma unroll
        for (int p = 0; p < 8; p++) {
            const int row = p * 32 + wr;
            cp16(sb + OFF_WS + (uint32_t)(row * KSPW + wc * 8) * 2,
                 (const void*)(g_wh + (size_t)row * FF + n0 + wc * 8));
        }
    }
    cp_commit();
    asm volatile("cp.async.wait_group 0;" ::: "memory");
    __syncthreads();

    const uint32_t a_lm = sb +
        (uint32_t)(((wm * 32 + (mt8 & 1) * 8 + r8) * KSPX + (mt8 >> 1) * 8) * 2);
    const uint32_t b_lm = sb + OFF_WS +
        (uint32_t)(((r8 + (mt8 & 1) * 8) * KSPW + wn * 16 + (mt8 >> 1) * 8) * 2);

    float acc[2][2][4];
    #pragma unroll
    for (int i = 0; i < 2; i++)
        #pragma unroll
        for (int j = 0; j < 2; j++)
            #pragma unroll
            for (int q = 0; q < 4; q++) acc[i][j][q] = 0.f;

    #pragma unroll
    for (int kk = 0; kk < 16; kk++) {
        uint32_t a0[4], a1[4], bf[4];
        ldm_x4(a0, a_lm + kk * 32);
        ldm_x4(a1, a_lm + kk * 32 + 16 * KSPX * 2);
        ldm_x4_t(bf, b_lm + (uint32_t)(kk * 16 * KSPW) * 2);
        mma_f16(acc[0][0], a0, bf[0], bf[1]);
        mma_f16(acc[0][1], a0, bf[2], bf[3]);
        mma_f16(acc[1][0], a1, bf[0], bf[1]);
        mma_f16(acc[1][1], a1, bf[2], bf[3]);
    }

    // epilogue: write fp16 y only
    #pragma unroll
    for (int mi = 0; mi < 2; mi++) {
        const int lm = wm * 32 + mi * 16 + g;
        #pragma unroll
        for (int nj = 0; nj < 2; nj++) {
            const int n = n0 + wn * 16 + nj * 8 + 2 * t;
            const float* cc = acc[mi][nj];
            *(__half2*)&g_yh[(size_t)(m0 + lm) * FF + n]     = __floats2half2_rn(cc[0], cc[1]);
            *(__half2*)&g_yh[(size_t)(m0 + lm + 8) * FF + n] = __floats2half2_rn(cc[2], cc[3]);
        }
    }
}

// ---------------- kernel B: partial C = adj[:, kslice] @ y[kslice] ----------------
// 256 thr, 8 warps (2m x 4n), warp tile 32x64, CTA 64x256, split-K x2, 4-stage ring.
__global__ void __launch_bounds__(256, 2) gcn_mma_kernel(
    const float* __restrict__ adj)
{
    extern __shared__ char smem[];
    __half* As = (__half*)(smem + OFF_AS);
    const uint32_t sb = smem_u32(smem);

    const int tid = threadIdx.x;
    const int wid = tid >> 5, lane = tid & 31;
    const int g = lane >> 2, t = lane & 3;
    const int wm = wid & 1, wn = wid >> 1;      // 2 m-warps x 4 n-warps
    const int m0 = blockIdx.x * MT;
    const int ksl = blockIdx.y;                 // 0 or 1
    const int k0 = ksl * KSPLIT;

    // A: 4 threads per row, 8 floats each (KS=32)
    const int ar = tid >> 2, acq = tid & 3;
    const float* aptr = adj + (size_t)(m0 + ar) * NN + k0 + acq * 8;
    __half* const a_st = As + ar * KSPA + acq * 8;
    // B: 32 threads per k-row, contiguous 16B; 8 rows/pass, 4 passes/stage
    const int br = tid >> 5, bq = tid & 31;
    const __half* bptr = g_yh + (size_t)(k0 + br) * FF + bq * 8;
    const uint32_t b_dst = sb + OFF_BS + (br * KSPB) * 2 + bq * 16;

    const int mt8 = lane >> 3, r8 = lane & 7;
    const uint32_t a_lm = sb + OFF_AS +
        (((wm * 32 + (mt8 & 1) * 8 + r8) * KSPA + (mt8 >> 1) * 8) * 2);
    const uint32_t b_lm = sb + OFF_BS +
        (((r8 + (mt8 & 1) * 8) * KSPB + wn * 64 + (mt8 >> 1) * 8) * 2);

    float rs_local = 0.f;
    float acc[2][8][4];
    #pragma unroll
    for (int i = 0; i < 2; i++)
        #pragma unroll
        for (int j = 0; j < 8; j++)
            #pragma unroll
            for (int q = 0; q < 4; q++) acc[i][j][q] = 0.f;

    float4 ra[2][2];

    // ---- prologue: B stages 0,1,2 via cp.async; A stages 0,1 via LDG ----
    #pragma unroll
    for (int s = 0; s < 3; s++) {
        #pragma unroll
        for (int c = 0; c < 4; c++)
            cp16(b_dst + s * BS_STAGE_B + c * (8 * KSPB * 2),
                 (const void*)(bptr + ((size_t)s * KS + c * 8) * FF));
        cp_commit();
    }
    #pragma unroll
    for (int s = 0; s < 2; s++) {
        ra[s][0] = *(const float4*)(aptr + (size_t)s * KS);
        ra[s][1] = *(const float4*)(aptr + (size_t)s * KS + 4);
    }
    {   // STS A stage 0 + rowsum
        const float4 v0 = ra[0][0], v1 = ra[0][1];
        rs_local += v0.x + v0.y + v0.z + v0.w + v1.x + v1.y + v1.z + v1.w;
        __half2 h[4];
        h[0] = __floats2half2_rn(v0.x, v0.y); h[1] = __floats2half2_rn(v0.z, v0.w);
        h[2] = __floats2half2_rn(v1.x, v1.y); h[3] = __floats2half2_rn(v1.z, v1.w);
        *(uint4*)a_st = make_uint4(*(uint32_t*)&h[0], *(uint32_t*)&h[1],
                                   *(uint32_t*)&h[2], *(uint32_t*)&h[3]);
    }

    // ---- main loop (single barrier, 4-stage B ring, 2 stages in flight) ----
    for (int i = 0; i < NITER; i++) {
        const int bbuf = i & 3;

        if (i + 2 < NITER) {
            const float* ap = aptr + (size_t)(i + 2) * KS;
            ra[i & 1][0] = *(const float4*)(ap);
            ra[i & 1][1] = *(const float4*)(ap + 4);
        }

        if (i < NITER - 2)       { asm volatile("cp.async.wait_group 2;" ::: "memory"); }
        else if (i == NITER - 2) { asm volatile("cp.async.wait_group 1;" ::: "memory"); }
        else                     { asm volatile("cp.async.wait_group 0;" ::: "memory"); }
        __syncthreads();

        if (i + 1 < NITER) {   // STS A stage i+1 + rowsum
            const float4 v0 = ra[(i + 1) & 1][0], v1 = ra[(i + 1) & 1][1];
            rs_local += v0.x + v0.y + v0.z + v0.w + v1.x + v1.y + v1.z + v1.w;
            __half2 h[4];
            h[0] = __floats2half2_rn(v0.x, v0.y); h[1] = __floats2half2_rn(v0.z, v0.w);
            h[2] = __floats2half2_rn(v1.x, v1.y); h[3] = __floats2half2_rn(v1.z, v1.w);
            *(uint4*)(a_st + ((i + 1) & 1) * AS_STAGE) = make_uint4(
                *(uint32_t*)&h[0], *(uint32_t*)&h[1], *(uint32_t*)&h[2], *(uint32_t*)&h[3]);
        }
        if (i + 3 < NITER) {   // cp.async B stage i+3 into buf (i+3)&3 (== i-1, free)
            const uint32_t bd = b_dst + ((i + 3) & 3) * BS_STAGE_B;
            const __half* bp = bptr + (size_t)(i + 3) * KS * FF;
            #pragma unroll
            for (int c = 0; c < 4; c++)
                cp16(bd + c * (8 * KSPB * 2), (const void*)(bp + (size_t)c * 8 * FF));
            cp_commit();
        }

        // ---- compute stage i (warp tile 32x64, 2 kk chunks) ----
        const uint32_t aB = a_lm + (i & 1) * AS_STAGE_B;
        const uint32_t bB = b_lm + bbuf * BS_STAGE_B;
        #pragma unroll
        for (int kk = 0; kk < 2; kk++) {
            uint32_t a0[4], a1[4];
            ldm_x4(a0, aB + kk * 32);
            ldm_x4(a1, aB + kk * 32 + 16 * KSPA * 2);
            uint32_t bf[4][4];
            #pragma unroll
            for (int j = 0; j < 4; j++)
                ldm_x4_t(bf[j], bB + (uint32_t)(kk * 16 * KSPB) * 2 + j * 32);
            #pragma unroll
            for (int j = 0; j < 4; j++) {
                mma_f16(acc[0][2 * j],     a0, bf[j][0], bf[j][1]);
                mma_f16(acc[0][2 * j + 1], a0, bf[j][2], bf[j][3]);
                mma_f16(acc[1][2 * j],     a1, bf[j][0], bf[j][1]);
                mma_f16(acc[1][2 * j + 1], a1, bf[j][2], bf[j][3]);
            }
        }
    }

    // ---- partial rowsum: 4 consecutive lanes per row ----
    float rs = rs_local;
    rs += __shfl_xor_sync(0xffffffffu, rs, 1);
    rs += __shfl_xor_sync(0xffffffffu, rs, 2);
    if ((tid & 3) == 0) g_rs[(size_t)ksl * NN + m0 + ar] = rs;

    // ---- write partial C ----
    float* pout = g_part + (size_t)ksl * NN * FF;
    #pragma unroll
    for (int mi = 0; mi < 2; mi++) {
        const int lm = wm * 32 + mi * 16 + g;
        #pragma unroll
        for (int nj = 0; nj < 8; nj++) {
            const int n = wn * 64 + nj * 8 + 2 * t;
            const float* cc = acc[mi][nj];
            *(float2*)&pout[(size_t)(m0 + lm) * FF + n]     = make_float2(cc[0], cc[1]);
            *(float2*)&pout[(size_t)(m0 + lm + 8) * FF + n] = make_float2(cc[2], cc[3]);
        }
    }
}

// ---------------- combine: out = scale*(P0+P1+beta*y) + bias ----------------
__global__ void __launch_bounds__(256) combine_kernel(
    const float* __restrict__ beta,
    const float* __restrict__ bias,
    float* __restrict__ out)
{
    const int idx = blockIdx.x * 256 + threadIdx.x;   // 1 thread = 4 floats
    const int m = idx >> 6;
    const int n = (idx & 63) * 4;
    const float be = beta[m];
    const float sc = 1.0f / (g_rs[m] + g_rs[NN + m] + be);
    const size_t off = (size_t)m * FF + n;
    const float4 p0 = *(const float4*)&g_part[off];
    const float4 p1 = *(const float4*)&g_part[(size_t)NN * FF + off];
    const uint2 yraw = *(const uint2*)&g_yh[off];     // 4 halves
    const float2 ya = __half22float2(*(const __half2*)&yraw.x);
    const float2 yb = __half22float2(*(const __half2*)&yraw.y);
    const float4 bv = *(const float4*)&bias[n];
    float4 o;
    o.x = sc * (p0.x + p1.x + be * ya.x) + bv.x;
    o.y = sc * (p0.y + p1.y + be * ya.y) + bv.y;
    o.z = sc * (p0.z + p1.z + be * yb.x) + bv.z;
    o.w = sc * (p0.w + p1.w + be * yb.y) + bv.w;
    *(float4*)&out[off] = o;
}

// ---------------- launch ----------------
extern "C" void kernel_launch(void* const* d_in, const int* in_sizes, int n_in,
                              void* d_out, int out_size)
{
    const float *x = nullptr, *adj = nullptr, *w = nullptr, *bias = nullptr, *beta = nullptr;
    for (int i = 0; i < n_in; i++) {
        switch (in_sizes[i]) {
            case NN * FF:   x    = (const float*)d_in[i]; break;
            case 67108864:  adj  = (const float*)d_in[i]; break;
            case FF * FF:   w    = (const float*)d_in[i]; break;
            case FF:        bias = (const float*)d_in[i]; break;
            case NN:        beta = (const float*)d_in[i]; break;
            default: break;
        }
    }
    float* out = (float*)d_out;

    cudaFuncSetAttribute(gcn_mma_kernel, cudaFuncAttributeMaxDynamicSharedMemorySize, SMEM_TOTAL);
    cudaFuncSetAttribute(gemm_y_kernel, cudaFuncAttributeMaxDynamicSharedMemorySize, SMEM_A_TOTAL);

    convert_kernel<<<(NN * FF / 8 + FF * FF / 8) / 256, 256>>>(x, w);
    gemm_y_kernel<<<dim3(NN / 64, 4), 256, SMEM_A_TOTAL>>>();
    gcn_mma_kernel<<<dim3(NN / MT, 2), 256, SMEM_TOTAL>>>(adj);
    combine_kernel<<<(NN * FF) / (256 * 4), 256>>>(beta, bias, out);
}